// round 6
// baseline (speedup 1.0000x reference)
#include <cuda_runtime.h>
#include <cstdint>

// Capsule layer, sliced producer/consumer pipeline:
//   prep:  permute W into tf32 mma fragment layout (once)
//   4x { conv_votes(slice) ; routing(slice) }  -- votes slice stays in L2
//
//   x [32,32,32,8,16] f32   W [8,3,3,16,128] f32   b [1,1,8,16] f32
//   out [32,32,32,8,16] f32
//
// votes scratch: one slice of 8192 px * 1024 f32 = 33.6 MB, reused by all
// 4 slices (L2-resident; next slice's writes overwrite before eviction).

#define EPS_SQ 1e-7f
#define XT_PITCH 232        // 232 % 32 == 8 -> conflict-free A-frag LDS

__device__ float    g_votes[8192 * 1024];
__device__ uint32_t g_Wfrag[8 * 18 * 16 * 64];

__device__ __forceinline__ uint32_t tf32_rna(float f) {
    uint32_t u;
    asm("cvt.rna.tf32.f32 %0, %1;" : "=r"(u) : "f"(f));
    return u;
}
__device__ __forceinline__ void mma8(float c[4], const uint4& a, const uint2& b) {
    asm volatile(
        "mma.sync.aligned.m16n8k8.row.col.f32.tf32.tf32.f32 "
        "{%0,%1,%2,%3}, {%4,%5,%6,%7}, {%8,%9}, {%0,%1,%2,%3};"
        : "+f"(c[0]), "+f"(c[1]), "+f"(c[2]), "+f"(c[3])
        : "r"(a.x), "r"(a.y), "r"(a.z), "r"(a.w), "r"(b.x), "r"(b.y));
}

// Pre-permuted tf32 weight fragments: [i][kk(18)][nt(16)][lane] uint2,
// (b0,b1) = W[k=8kk+c4][cf=8nt+g], W[k+4][cf].  (g=lane>>2, c4=lane&3)
__global__ void prep_weights(const float* __restrict__ W) {
    int gi = blockIdx.x * 256 + threadIdx.x;      // 0..73727
    int lane = gi & 31;
    int nt   = (gi >> 5) & 15;
    int r    = gi >> 9;                           // i*18 + kk
    int kk = r % 18, i = r / 18;
    int g = lane >> 2, c4 = lane & 3;
    int cf = nt * 8 + g;
    int k0 = kk * 8 + c4, k1 = k0 + 4;
    float w0 = W[((i * 9 + (k0 >> 4)) * 16 + (k0 & 15)) * 128 + cf];
    float w1 = W[((i * 9 + (k1 >> 4)) * 16 + (k1 & 15)) * 128 + cf];
    uint2 o;
    o.x = tf32_rna(w0);
    o.y = tf32_rna(w1);
    reinterpret_cast<uint2*>(g_Wfrag)[gi] = o;
}

// ---- K1: conv votes GEMM for one slice (64 m-blocks x 8 i) ----
// Block = 128 px (4 h-rows x 32 w), 128 cf, one input capsule i.
// M=128 (4 wm x 2 mt x m16), N=128 (2 wn x 8 n8), K=144 (18 k8).
__global__ __launch_bounds__(256, 2)
void conv_votes_kernel(const float* __restrict__ x, int slice)
{
    __shared__ float x_t[16 * XT_PITCH];   // [fin 16][6 rows * 34 cols]

    const int t = threadIdx.x, lane = t & 31, wid = t >> 5;
    const int mblk = slice * 64 + blockIdx.x, i = blockIdx.y;
    const int b = mblk >> 3, h0 = (mblk & 7) << 2;

    // load x tile transposed, zero-pad SAME borders
    for (int e4 = t; e4 < 816; e4 += 256) {
        int pix = e4 >> 2, q = e4 & 3;
        int r = pix / 34, c = pix - r * 34;
        int hh = h0 + r - 1, ww = c - 1;
        float4 v = make_float4(0.f, 0.f, 0.f, 0.f);
        if (hh >= 0 && hh < 32 && ww >= 0 && ww < 32)
            v = reinterpret_cast<const float4*>(x)
                  [((b * 32 + hh) * 32 + ww) * 32 + i * 4 + q];
        x_t[(q * 4 + 0) * XT_PITCH + pix] = v.x;
        x_t[(q * 4 + 1) * XT_PITCH + pix] = v.y;
        x_t[(q * 4 + 2) * XT_PITCH + pix] = v.z;
        x_t[(q * 4 + 3) * XT_PITCH + pix] = v.w;
    }
    __syncthreads();

    const int g = lane >> 2, c4 = lane & 3;
    const int wm = wid >> 1, wn = wid & 1;

    float acc[2][8][4];
    #pragma unroll
    for (int mt = 0; mt < 2; mt++)
        #pragma unroll
        for (int n = 0; n < 8; n++)
            #pragma unroll
            for (int j = 0; j < 4; j++) acc[mt][n][j] = 0.f;

    const uint2* wf = reinterpret_cast<const uint2*>(g_Wfrag) +
                      (i * 18 * 16 + wn * 8) * 32 + lane;

    #pragma unroll 3
    for (int kk = 0; kk < 18; kk++) {
        const int kyx = kk >> 1;
        const int ky = kyx / 3, kx = kyx - ky * 3;
        const int fin0 = ((kk & 1) << 3) + c4;
        uint4 a[2];
        #pragma unroll
        for (int mt = 0; mt < 2; mt++) {
            const float* xp = x_t + fin0 * XT_PITCH +
                              (wm + ky) * 34 + mt * 16 + g + kx;
            a[mt].x = tf32_rna(xp[0]);
            a[mt].y = tf32_rna(xp[8]);
            a[mt].z = tf32_rna(xp[4 * XT_PITCH]);
            a[mt].w = tf32_rna(xp[4 * XT_PITCH + 8]);
        }
        #pragma unroll
        for (int n = 0; n < 8; n++) {
            uint2 bb = wf[(kk * 16 + n) * 32];
            mma8(acc[0][n], a[0], bb);
            mma8(acc[1][n], a[1], bb);
        }
    }

    // store votes (slice-local): [px_local][i*128 + cf]
    float* vp = g_votes + (size_t)(blockIdx.x * 128) * 1024 +
                i * 128 + wn * 64 + 2 * c4;
    #pragma unroll
    for (int mt = 0; mt < 2; mt++) {
        const int m0 = wm * 32 + mt * 16 + g;
        #pragma unroll
        for (int n = 0; n < 8; n++) {
            float* p0 = vp + (size_t)m0 * 1024 + n * 8;
            *reinterpret_cast<float2*>(p0) =
                make_float2(acc[mt][n][0], acc[mt][n][1]);
            *reinterpret_cast<float2*>(p0 + 8 * 1024) =
                make_float2(acc[mt][n][2], acc[mt][n][3]);
        }
    }
}

// ---- K2: routing for one slice. 1024 blocks x 256 thr; warp = 1 px ----
__global__ __launch_bounds__(256)
void routing_kernel(const float* __restrict__ bias, float* __restrict__ out,
                    int slice)
{
    const int t = threadIdx.x, lane = t & 31, wid = t >> 5;
    const int pxl = blockIdx.x * 8 + wid;           // slice-local pixel
    const int px  = slice * 8192 + pxl;             // global pixel

    const float4 bv = reinterpret_cast<const float4*>(bias)[lane];
    const float4* vg = reinterpret_cast<const float4*>(g_votes) + (size_t)pxl * 256;

    float4 v[8];
    #pragma unroll
    for (int i = 0; i < 8; i++)
        v[i] = vg[i * 32 + lane];

    float logit[8];
    #pragma unroll
    for (int i = 0; i < 8; i++) logit[i] = 0.f;
    float4 act = make_float4(0.f, 0.f, 0.f, 0.f);

    #pragma unroll
    for (int r = 0; r < 3; r++) {
        float route[8];
        if (r == 0) {
            #pragma unroll
            for (int i = 0; i < 8; i++) route[i] = 0.125f;   // softmax(0)
        } else {
            #pragma unroll
            for (int i = 0; i < 8; i++) {
                float m = logit[i];
                m = fmaxf(m, __shfl_xor_sync(0xffffffffu, m, 4));
                m = fmaxf(m, __shfl_xor_sync(0xffffffffu, m, 8));
                m = fmaxf(m, __shfl_xor_sync(0xffffffffu, m, 16));
                float e = __expf(logit[i] - m);
                float s = e;
                s += __shfl_xor_sync(0xffffffffu, s, 4);
                s += __shfl_xor_sync(0xffffffffu, s, 8);
                s += __shfl_xor_sync(0xffffffffu, s, 16);
                route[i] = e / s;
            }
        }
        float4 pre = bv;
        #pragma unroll
        for (int i = 0; i < 8; i++) {
            pre.x += route[i] * v[i].x;
            pre.y += route[i] * v[i].y;
            pre.z += route[i] * v[i].z;
            pre.w += route[i] * v[i].w;
        }
        float s2 = pre.x * pre.x + pre.y * pre.y + pre.z * pre.z + pre.w * pre.w;
        s2 += __shfl_xor_sync(0xffffffffu, s2, 1);
        s2 += __shfl_xor_sync(0xffffffffu, s2, 2);
        float scale = s2 / (1.f + s2) * rsqrtf(s2 + EPS_SQ);
        act.x = scale * pre.x;
        act.y = scale * pre.y;
        act.z = scale * pre.z;
        act.w = scale * pre.w;
        if (r < 2) {
            #pragma unroll
            for (int i = 0; i < 8; i++) {
                float d = v[i].x * act.x + v[i].y * act.y +
                          v[i].z * act.z + v[i].w * act.w;
                d += __shfl_xor_sync(0xffffffffu, d, 1);
                d += __shfl_xor_sync(0xffffffffu, d, 2);
                logit[i] += d;
            }
        }
    }

    reinterpret_cast<float4*>(out)[(size_t)px * 32 + lane] = act;
}

extern "C" void kernel_launch(void* const* d_in, const int* in_sizes, int n_in,
                              void* d_out, int out_size)
{
    const float* x    = (const float*)d_in[0];
    const float* Wt   = (const float*)d_in[1];
    const float* bias = (const float*)d_in[2];
    float* out = (float*)d_out;
    (void)in_sizes; (void)n_in; (void)out_size;

    prep_weights<<<288, 256>>>(Wt);
    for (int s = 0; s < 4; s++) {
        dim3 gridA(64, 8);
        conv_votes_kernel<<<gridA, 256>>>(x, s);
        routing_kernel<<<1024, 256>>>(bias, out, s);
    }
}

// round 7
// speedup vs baseline: 1.1662x; 1.1662x over previous
#include <cuda_runtime.h>
#include <cstdint>

// Capsule layer, two-kernel split (R6):
//   prep:  permute W into tf32 mma fragment layout (once)
//   conv:  tf32 mma.sync GEMM votes[i][128px,128cf]; W frags staged in smem,
//          x tile pre-converted to tf32 (no in-loop cvt, no in-loop LDG)
//   routing: fp32 dynamic routing, one warp per pixel
//
//   x [32,32,32,8,16] f32   W [8,3,3,16,128] f32   b [1,1,8,16] f32
//   out [32,32,32,8,16] f32

#define EPS_SQ 1e-7f
#define XT_PITCH 232        // 232 % 32 == 8 -> conflict-free A-frag LDS

__device__ float    g_votes[32768 * 1024];           // [px][i*128+cf]
__device__ uint32_t g_Wfrag[8 * 18 * 16 * 64];

__device__ __forceinline__ uint32_t tf32_rna(float f) {
    uint32_t u;
    asm("cvt.rna.tf32.f32 %0, %1;" : "=r"(u) : "f"(f));
    return u;
}
__device__ __forceinline__ void mma8(float c[4], const uint4& a, const uint2& b) {
    asm volatile(
        "mma.sync.aligned.m16n8k8.row.col.f32.tf32.tf32.f32 "
        "{%0,%1,%2,%3}, {%4,%5,%6,%7}, {%8,%9}, {%0,%1,%2,%3};"
        : "+f"(c[0]), "+f"(c[1]), "+f"(c[2]), "+f"(c[3])
        : "r"(a.x), "r"(a.y), "r"(a.z), "r"(a.w), "r"(b.x), "r"(b.y));
}

// Pre-permuted tf32 weight fragments: [i][kk(18)][nt(16)][lane] uint2,
// (b0,b1) = W[k=8kk+c4][cf=8nt+g], W[k+4][cf].  (g=lane>>2, c4=lane&3)
__global__ void prep_weights(const float* __restrict__ W) {
    int gi = blockIdx.x * 256 + threadIdx.x;      // 0..73727
    int lane = gi & 31;
    int nt   = (gi >> 5) & 15;
    int r    = gi >> 9;                           // i*18 + kk
    int kk = r % 18, i = r / 18;
    int g = lane >> 2, c4 = lane & 3;
    int cf = nt * 8 + g;
    int k0 = kk * 8 + c4, k1 = k0 + 4;
    float w0 = W[((i * 9 + (k0 >> 4)) * 16 + (k0 & 15)) * 128 + cf];
    float w1 = W[((i * 9 + (k1 >> 4)) * 16 + (k1 & 15)) * 128 + cf];
    uint2 o;
    o.x = tf32_rna(w0);
    o.y = tf32_rna(w1);
    reinterpret_cast<uint2*>(g_Wfrag)[gi] = o;
}

// ---- K1: conv votes GEMM. grid (256 m-blocks, 8 i), 256 threads ----
// Block = 128 px (4 h-rows x 32 w of batch mblk>>3), 128 cf, one capsule i.
// M=128 (4 wm x 2 mt x m16), N=128 (2 wn x 8 n8), K=144 (18 k8).
__global__ __launch_bounds__(256, 2)
void conv_votes_kernel(const float* __restrict__ x)
{
    __shared__ uint32_t x_t[16 * XT_PITCH];          // tf32 bits, [fin][6*34 pix]
    __shared__ uint2    s_w[18 * 16 * 32];           // W frags for this i (72 KB)

    const int t = threadIdx.x, lane = t & 31, wid = t >> 5;
    const int mblk = blockIdx.x, i = blockIdx.y;
    const int b = mblk >> 3, h0 = (mblk & 7) << 2;

    // stage W fragments: 4608 uint4, 18 per thread
    {
        const uint4* gw4 = reinterpret_cast<const uint4*>(g_Wfrag) + i * 4608;
        uint4* sw4 = reinterpret_cast<uint4*>(s_w);
        #pragma unroll
        for (int j = 0; j < 18; j++)
            sw4[j * 256 + t] = gw4[j * 256 + t];
    }

    // load x tile transposed + tf32-convert, zero-pad SAME borders
    for (int e4 = t; e4 < 816; e4 += 256) {
        int pix = e4 >> 2, q = e4 & 3;
        int r = pix / 34, c = pix - r * 34;
        int hh = h0 + r - 1, ww = c - 1;
        float4 v = make_float4(0.f, 0.f, 0.f, 0.f);
        if (hh >= 0 && hh < 32 && ww >= 0 && ww < 32)
            v = reinterpret_cast<const float4*>(x)
                  [((b * 32 + hh) * 32 + ww) * 32 + i * 4 + q];
        x_t[(q * 4 + 0) * XT_PITCH + pix] = tf32_rna(v.x);
        x_t[(q * 4 + 1) * XT_PITCH + pix] = tf32_rna(v.y);
        x_t[(q * 4 + 2) * XT_PITCH + pix] = tf32_rna(v.z);
        x_t[(q * 4 + 3) * XT_PITCH + pix] = tf32_rna(v.w);
    }
    __syncthreads();

    const int g = lane >> 2, c4 = lane & 3;
    const int wm = wid >> 1, wn = wid & 1;

    float acc[2][8][4];
    #pragma unroll
    for (int mt = 0; mt < 2; mt++)
        #pragma unroll
        for (int n = 0; n < 8; n++)
            #pragma unroll
            for (int j = 0; j < 4; j++) acc[mt][n][j] = 0.f;

    const uint2* wfs = s_w + wn * 8 * 32 + lane;

    #pragma unroll 6
    for (int kk = 0; kk < 18; kk++) {
        const int kyx = kk >> 1;
        const int ky = kyx / 3, kx = kyx - ky * 3;
        const int fin0 = ((kk & 1) << 3) + c4;
        uint4 a[2];
        #pragma unroll
        for (int mt = 0; mt < 2; mt++) {
            const uint32_t* xp = x_t + fin0 * XT_PITCH +
                                 (wm + ky) * 34 + mt * 16 + g + kx;
            a[mt].x = xp[0];
            a[mt].y = xp[8];
            a[mt].z = xp[4 * XT_PITCH];
            a[mt].w = xp[4 * XT_PITCH + 8];
        }
        #pragma unroll
        for (int n = 0; n < 8; n++) {
            uint2 bb = wfs[(kk * 16 + n) * 32];
            mma8(acc[0][n], a[0], bb);
            mma8(acc[1][n], a[1], bb);
        }
    }

    // store votes: [px][i*128 + cf]
    float* vp = g_votes + (size_t)(mblk * 128) * 1024 +
                i * 128 + wn * 64 + 2 * c4;
    #pragma unroll
    for (int mt = 0; mt < 2; mt++) {
        const int m0 = wm * 32 + mt * 16 + g;
        #pragma unroll
        for (int n = 0; n < 8; n++) {
            float* p0 = vp + (size_t)m0 * 1024 + n * 8;
            *reinterpret_cast<float2*>(p0) =
                make_float2(acc[mt][n][0], acc[mt][n][1]);
            *reinterpret_cast<float2*>(p0 + 8 * 1024) =
                make_float2(acc[mt][n][2], acc[mt][n][3]);
        }
    }
}

// ---- K2: routing. grid 4096, 256 threads; warp w routes px = blk*8+w ----
__global__ __launch_bounds__(256)
void routing_kernel(const float* __restrict__ bias, float* __restrict__ out)
{
    const int t = threadIdx.x, lane = t & 31, wid = t >> 5;
    const int px = blockIdx.x * 8 + wid;

    const float4 bv = reinterpret_cast<const float4*>(bias)[lane];
    const float4* vg = reinterpret_cast<const float4*>(g_votes) + (size_t)px * 256;

    float4 v[8];
    #pragma unroll
    for (int i = 0; i < 8; i++)
        v[i] = vg[i * 32 + lane];

    float logit[8];
    #pragma unroll
    for (int i = 0; i < 8; i++) logit[i] = 0.f;
    float4 act = make_float4(0.f, 0.f, 0.f, 0.f);

    #pragma unroll
    for (int r = 0; r < 3; r++) {
        float route[8];
        if (r == 0) {
            #pragma unroll
            for (int i = 0; i < 8; i++) route[i] = 0.125f;   // softmax(0)
        } else {
            #pragma unroll
            for (int i = 0; i < 8; i++) {
                float m = logit[i];
                m = fmaxf(m, __shfl_xor_sync(0xffffffffu, m, 4));
                m = fmaxf(m, __shfl_xor_sync(0xffffffffu, m, 8));
                m = fmaxf(m, __shfl_xor_sync(0xffffffffu, m, 16));
                float e = __expf(logit[i] - m);
                float s = e;
                s += __shfl_xor_sync(0xffffffffu, s, 4);
                s += __shfl_xor_sync(0xffffffffu, s, 8);
                s += __shfl_xor_sync(0xffffffffu, s, 16);
                route[i] = e / s;
            }
        }
        float4 pre = bv;
        #pragma unroll
        for (int i = 0; i < 8; i++) {
            pre.x += route[i] * v[i].x;
            pre.y += route[i] * v[i].y;
            pre.z += route[i] * v[i].z;
            pre.w += route[i] * v[i].w;
        }
        float s2 = pre.x * pre.x + pre.y * pre.y + pre.z * pre.z + pre.w * pre.w;
        s2 += __shfl_xor_sync(0xffffffffu, s2, 1);
        s2 += __shfl_xor_sync(0xffffffffu, s2, 2);
        float scale = s2 / (1.f + s2) * rsqrtf(s2 + EPS_SQ);
        act.x = scale * pre.x;
        act.y = scale * pre.y;
        act.z = scale * pre.z;
        act.w = scale * pre.w;
        if (r < 2) {
            #pragma unroll
            for (int i = 0; i < 8; i++) {
                float d = v[i].x * act.x + v[i].y * act.y +
                          v[i].z * act.z + v[i].w * act.w;
                d += __shfl_xor_sync(0xffffffffu, d, 1);
                d += __shfl_xor_sync(0xffffffffu, d, 2);
                logit[i] += d;
            }
        }
    }

    reinterpret_cast<float4*>(out)[(size_t)px * 32 + lane] = act;
}

extern "C" void kernel_launch(void* const* d_in, const int* in_sizes, int n_in,
                              void* d_out, int out_size)
{
    const float* x    = (const float*)d_in[0];
    const float* Wt   = (const float*)d_in[1];
    const float* bias = (const float*)d_in[2];
    float* out = (float*)d_out;
    (void)in_sizes; (void)n_in; (void)out_size;

    prep_weights<<<288, 256>>>(Wt);
    dim3 gridA(256, 8);
    conv_votes_kernel<<<gridA, 256>>>(x);
    routing_kernel<<<4096, 256>>>(bias, out);
}